// round 13
// baseline (speedup 1.0000x reference)
#include <cuda_runtime.h>
#include <math.h>
#include <float.h>

#define Bn    8
#define Hn    96
#define Wn    96
#define HWn   9216
#define FCn   768
#define Rn    12
#define Pn    16
#define KSn   13
#define TOPKn 24

typedef unsigned long long ull;

// ---------------- scratch (device globals) ----------------
__device__ float g_t1[Bn*Rn*HWn];
__device__ float g_proj[Bn*Rn*HWn];
__device__ float g_canvas[Bn*Rn*HWn];
__device__ float g_occraw[Bn*HWn];
__device__ float g_sup[Bn*HWn];
__device__ float g_occ[Bn*HWn];
__device__ float g_dnorm[Bn*HWn];
__device__ float g_anch[Bn*HWn];

// ---------------- helpers ----------------
__device__ __forceinline__ void ffma2(ull &acc, ull a, ull b) {
    asm("fma.rn.f32x2 %0, %1, %2, %0;" : "+l"(acc) : "l"(a), "l"(b));
}
__device__ __forceinline__ ull dup2(float x) {
    ull r;
    asm("mov.b64 %0, {%1, %1};" : "=l"(r) : "f"(x));
    return r;
}
__device__ __forceinline__ float2 unpack2(ull v) {
    float2 r;
    asm("mov.b64 {%0, %1}, %2;" : "=f"(r.x), "=f"(r.y) : "l"(v));
    return r;
}
__device__ __forceinline__ float gelu_exact(float x) {
    return 0.5f * x * (1.0f + erff(x * 0.70710678118654752440f));
}

// ---------------- diagnostic slot-shifters (empty, ~1-2us each) ----------------
__global__ void k_nop0() {}
__global__ void k_nop1() {}
__global__ void k_nop2() {}

// ---------------- K1: conv1x1 FC->R + gelu (2 px/thread, 3-buffer LDG pipeline) ----------------
__global__ void __launch_bounds__(256) k_conv1(const float* __restrict__ feat,
                                               const float* __restrict__ w1,
                                               const float* __restrict__ b1) {
    __shared__ __align__(16) float sw[FCn*Rn];   // [c][r] contiguous 12 floats/channel
    for (int i = threadIdx.x; i < FCn*Rn; i += 256) {
        int c = i / Rn, r = i - c*Rn;
        sw[i] = w1[r*FCn + c];
    }
    __syncthreads();
    int b  = blockIdx.x / 18;
    int p0 = (blockIdx.x % 18) * 512 + threadIdx.x * 2;
    const float* fb = feat + (size_t)b * FCn * HWn + p0;

    ull acc0[6], acc1[6];
#pragma unroll
    for (int j = 0; j < 6; j++) { acc0[j] = 0ull; acc1[j] = 0ull; }

    const ulonglong2* wv = (const ulonglong2*)sw;  // 3 per channel

#define LOAD8(X, CH) do { \
    _Pragma("unroll") \
    for (int u_ = 0; u_ < 8; u_++) X[u_] = *(const float2*)(fb + (size_t)((CH) + u_) * HWn); \
} while (0)
#define COMP8(X, CH) do { \
    _Pragma("unroll") \
    for (int u_ = 0; u_ < 8; u_++) { \
        ull d0_ = dup2(X[u_].x); \
        ull d1_ = dup2(X[u_].y); \
        const ulonglong2* w_ = wv + ((CH) + u_) * 3; \
        ulonglong2 q0 = w_[0], q1 = w_[1], q2 = w_[2]; \
        ffma2(acc0[0], d0_, q0.x); ffma2(acc1[0], d1_, q0.x); \
        ffma2(acc0[1], d0_, q0.y); ffma2(acc1[1], d1_, q0.y); \
        ffma2(acc0[2], d0_, q1.x); ffma2(acc1[2], d1_, q1.x); \
        ffma2(acc0[3], d0_, q1.y); ffma2(acc1[3], d1_, q1.y); \
        ffma2(acc0[4], d0_, q2.x); ffma2(acc1[4], d1_, q2.x); \
        ffma2(acc0[5], d0_, q2.y); ffma2(acc1[5], d1_, q2.y); \
    } \
} while (0)

    float2 A[8], B[8], C[8];
    LOAD8(A, 0); LOAD8(B, 8); LOAD8(C, 16);
    int cb = 0;
#pragma unroll 1
    for (int it = 0; it < 31; it++) {
        COMP8(A, cb);      LOAD8(A, cb + 24);
        COMP8(B, cb + 8);  LOAD8(B, cb + 32);
        COMP8(C, cb + 16); LOAD8(C, cb + 40);
        cb += 24;
    }
    COMP8(A, 744); COMP8(B, 752); COMP8(C, 760);
#undef LOAD8
#undef COMP8

    float* op = g_t1 + (size_t)b * Rn * HWn + p0;
#pragma unroll
    for (int j = 0; j < 6; j++) {
        float2 a0 = unpack2(acc0[j]);
        float2 a1 = unpack2(acc1[j]);
        float bias0 = __ldg(b1 + 2*j), bias1 = __ldg(b1 + 2*j + 1);
        float2 s0; s0.x = gelu_exact(a0.x + bias0); s0.y = gelu_exact(a1.x + bias0);
        float2 s1; s1.x = gelu_exact(a0.y + bias1); s1.y = gelu_exact(a1.y + bias1);
        *(float2*)(op + (size_t)(2*j)     * HWn) = s0;
        *(float2*)(op + (size_t)(2*j + 1) * HWn) = s1;
    }
}

// ---------------- K2: conv3x3 R->R + gelu + occ_raw + canvas zero ----------------
__global__ void __launch_bounds__(256) k_conv2(const float* __restrict__ w2,
                                               const float* __restrict__ b2) {
    __shared__ float tile[Rn][18*18];
    __shared__ __align__(16) float sw2[Rn*Rn*9];
    __shared__ __align__(16) float sb2[Rn];
    int b   = blockIdx.z;
    int ty0 = blockIdx.y * 16, tx0 = blockIdx.x * 16;
    for (int i = threadIdx.x; i < Rn*Rn*9; i += 256) {
        int rout = i % 12;
        int rest = i / 12;
        int rin  = rest / 9;
        int k9   = rest % 9;
        sw2[i] = w2[(rout*12 + rin) * 9 + k9];
    }
    if (threadIdx.x < Rn) sb2[threadIdx.x] = b2[threadIdx.x];
    const float* tin = g_t1 + (size_t)b * Rn * HWn;
    for (int i = threadIdx.x; i < Rn*324; i += 256) {
        int ch = i / 324, rem = i - ch*324;
        int yy = rem / 18, xx = rem % 18;
        int gy = ty0 + yy - 1, gx = tx0 + xx - 1;
        float v = 0.0f;
        if (gy >= 0 && gy < Hn && gx >= 0 && gx < Wn)
            v = tin[(size_t)ch * HWn + gy*Wn + gx];
        tile[ch][rem] = v;
    }
    __syncthreads();
    int ty = threadIdx.x / 16, tx = threadIdx.x % 16;
    ull acc[6];
    {
        const ull* bb = (const ull*)sb2;
#pragma unroll
        for (int j = 0; j < 6; j++) acc[j] = bb[j];
    }
    const ulonglong2* wv = (const ulonglong2*)sw2;
#pragma unroll
    for (int rin = 0; rin < 12; rin++) {
#pragma unroll
        for (int k9 = 0; k9 < 9; k9++) {
            int ky = k9 / 3, kx = k9 % 3;
            ull d = dup2(tile[rin][(ty + ky)*18 + tx + kx]);
            const ulonglong2* w = wv + (rin*9 + k9) * 3;
            ulonglong2 w0 = w[0], w1v = w[1], w2v = w[2];
            ffma2(acc[0], d, w0.x);  ffma2(acc[1], d, w0.y);
            ffma2(acc[2], d, w1v.x); ffma2(acc[3], d, w1v.y);
            ffma2(acc[4], d, w2v.x); ffma2(acc[5], d, w2v.y);
        }
    }
    int p = (ty0 + ty)*Wn + tx0 + tx;
    float* pout = g_proj + (size_t)b * Rn * HWn + p;
    float* cz   = g_canvas + (size_t)b * Rn * HWn + p;
    float asum = 0.0f;
#pragma unroll
    for (int j = 0; j < 6; j++) {
        float2 a = unpack2(acc[j]);
        float g0 = gelu_exact(a.x), g1 = gelu_exact(a.y);
        pout[(size_t)(2*j)     * HWn] = g0;
        pout[(size_t)(2*j + 1) * HWn] = g1;
        cz[(size_t)(2*j)     * HWn] = 0.0f;
        cz[(size_t)(2*j + 1) * HWn] = 0.0f;
        asum += fabsf(g0) + fabsf(g1);
    }
    g_occraw[b*HWn + p] = asum * (1.0f / 12.0f);
}

// ---------------- fused support/NMS/top-k/proto/stamp (1 block per batch) ----------------
__device__ __forceinline__ float win3max_s(const float* S, int y, int x) {
    float r = -FLT_MAX;
#pragma unroll
    for (int dy = -1; dy <= 1; dy++) {
        int yy = y + dy; if (yy < 0 || yy >= Hn) continue;
#pragma unroll
        for (int dx = -1; dx <= 1; dx++) {
            int xx = x + dx; if (xx < 0 || xx >= Wn) continue;
            r = fmaxf(r, S[yy*Wn + xx]);
        }
    }
    return r;
}
__device__ __forceinline__ float win3min_s(const float* S, int y, int x) {
    float r = FLT_MAX;
#pragma unroll
    for (int dy = -1; dy <= 1; dy++) {
        int yy = y + dy; if (yy < 0 || yy >= Hn) continue;
#pragma unroll
        for (int dx = -1; dx <= 1; dx++) {
            int xx = x + dx; if (xx < 0 || xx >= Wn) continue;
            r = fminf(r, S[yy*Wn + xx]);
        }
    }
    return r;
}
__device__ __forceinline__ float win3sum_s(const float* S, int y, int x) {
    float r = 0.0f;
#pragma unroll
    for (int dy = -1; dy <= 1; dy++) {
        int yy = y + dy; if (yy < 0 || yy >= Hn) continue;
#pragma unroll
        for (int dx = -1; dx <= 1; dx++) {
            int xx = x + dx; if (xx < 0 || xx >= Wn) continue;
            r += S[yy*Wn + xx];
        }
    }
    return r;
}

__device__ __constant__ float c_lenL[4] = {0.4f, 0.7f, 1.0f, 1.25f};
__device__ __constant__ float c_widL[4] = {0.12f, 0.18f, 0.24f, 0.3f};

__global__ void __launch_bounds__(1024) k_fused(const float* __restrict__ carrier,
                                                const float* __restrict__ density,
                                                const float* __restrict__ proto) {
    __shared__ float S[HWn];
    __shared__ float smn[32], smx[32];
    __shared__ float rv[32];
    __shared__ int   ri[32];
    __shared__ float sprot[Pn*Rn];
    __shared__ float s_val[TOPKn];
    __shared__ int   s_idx[TOPKn];
    __shared__ int   spidx[TOPKn];
    __shared__ int   s_bi;

    int b = blockIdx.x, tid = threadIdx.x;
    int lane = tid & 31, warp = tid >> 5;
    const size_t base = (size_t)b * HWn;

    if (tid < Pn*Rn) sprot[tid] = proto[tid];

    float dreg[9], oreg[9];
    float dmn = FLT_MAX, dmx = -FLT_MAX, omn = FLT_MAX, omx = -FLT_MAX;
#pragma unroll
    for (int j = 0; j < 9; j++) {
        int px = tid + j*1024;
        float d = density[base + px];
        float o = g_occraw[base + px];
        dreg[j] = d; oreg[j] = o;
        dmn = fminf(dmn, d); dmx = fmaxf(dmx, d);
        omn = fminf(omn, o); omx = fmaxf(omx, o);
        S[px] = fabsf(carrier[base + px]);
    }
#pragma unroll
    for (int off = 16; off; off >>= 1) {
        dmn = fminf(dmn, __shfl_down_sync(0xffffffffu, dmn, off));
        dmx = fmaxf(dmx, __shfl_down_sync(0xffffffffu, dmx, off));
        omn = fminf(omn, __shfl_down_sync(0xffffffffu, omn, off));
        omx = fmaxf(omx, __shfl_down_sync(0xffffffffu, omx, off));
    }
    if (!lane) { smn[warp] = dmn; smx[warp] = dmx; rv[warp] = omn; ri[warp] = __float_as_int(omx); }
    __syncthreads();
    if (tid < 32) {
        float a = smn[lane], c = smx[lane], e = rv[lane], f = __int_as_float(ri[lane]);
#pragma unroll
        for (int off = 16; off; off >>= 1) {
            a = fminf(a, __shfl_down_sync(0xffffffffu, a, off));
            c = fmaxf(c, __shfl_down_sync(0xffffffffu, c, off));
            e = fminf(e, __shfl_down_sync(0xffffffffu, e, off));
            f = fmaxf(f, __shfl_down_sync(0xffffffffu, f, off));
        }
        if (!lane) { smn[0] = a; smx[0] = c; rv[0] = e; ri[0] = __float_as_int(f); }
    }
    __syncthreads();
    dmn = smn[0]; dmx = smx[0]; omn = rv[0]; omx = __int_as_float(ri[0]);
    __syncthreads();

    float cav[9];
    float cmn = FLT_MAX, cmx = -FLT_MAX;
#pragma unroll
    for (int j = 0; j < 9; j++) {
        int px = tid + j*1024;
        int y = px / Wn, x = px - y*Wn;
        float v = win3sum_s(S, y, x) * (1.0f / 9.0f);
        cav[j] = v;
        cmn = fminf(cmn, v); cmx = fmaxf(cmx, v);
    }
#pragma unroll
    for (int off = 16; off; off >>= 1) {
        cmn = fminf(cmn, __shfl_down_sync(0xffffffffu, cmn, off));
        cmx = fmaxf(cmx, __shfl_down_sync(0xffffffffu, cmx, off));
    }
    if (!lane) { smn[warp] = cmn; smx[warp] = cmx; }
    __syncthreads();
    if (tid < 32) {
        float a = smn[lane], c = smx[lane];
#pragma unroll
        for (int off = 16; off; off >>= 1) {
            a = fminf(a, __shfl_down_sync(0xffffffffu, a, off));
            c = fmaxf(c, __shfl_down_sync(0xffffffffu, c, off));
        }
        if (!lane) { smn[0] = a; smx[0] = c; }
    }
    __syncthreads();
    cmn = smn[0]; cmx = smx[0];

    float dinv = 1.0f / fmaxf(dmx - dmn, 1e-6f);
    float oinv = 1.0f / fmaxf(omx - omn, 1e-6f);
    float cinv = 1.0f / fmaxf(cmx - cmn, 1e-6f);

    float occ[9], mval[9];
#pragma unroll
    for (int j = 0; j < 9; j++) {
        int px = tid + j*1024;
        float dn = (dreg[j] - dmn) * dinv;
        float oc = (oreg[j] - omn) * oinv;
        float cs = (cav[j] - cmn) * cinv;
        g_dnorm[base + px] = dn;
        g_occ[base + px] = oc;
        occ[j] = oc;
        float ev = 0.8f * cs + 0.2f * dn;
        mval[j] = (ev >= 0.28f) ? 1.0f : 0.0f;
    }
    __syncthreads();
#pragma unroll
    for (int j = 0; j < 9; j++) S[tid + j*1024] = mval[j];
    __syncthreads();
    float er[9];
#pragma unroll
    for (int j = 0; j < 9; j++) {
        int px = tid + j*1024;
        er[j] = win3min_s(S, px / Wn, px % Wn);
    }
    __syncthreads();
#pragma unroll
    for (int j = 0; j < 9; j++) S[tid + j*1024] = er[j];
    __syncthreads();
    float op[9];
#pragma unroll
    for (int j = 0; j < 9; j++) {
        int px = tid + j*1024;
        op[j] = fminf(fmaxf(win3max_s(S, px / Wn, px % Wn), 0.0f), 1.0f);
    }
    __syncthreads();
#pragma unroll
    for (int j = 0; j < 9; j++) S[tid + j*1024] = op[j];
    __syncthreads();
    float sc[9];
#pragma unroll
    for (int j = 0; j < 9; j++) {
        int px = tid + j*1024;
        float sp = fminf(fmaxf(win3max_s(S, px / Wn, px % Wn), 0.0f), 1.0f);
        g_sup[base + px] = sp;
        sc[j] = occ[j] * sp;
    }
    __syncthreads();
#pragma unroll
    for (int j = 0; j < 9; j++) S[tid + j*1024] = sc[j];
    __syncthreads();
    float masked[9];
#pragma unroll
    for (int j = 0; j < 9; j++) {
        int px = tid + j*1024;
        float lm = win3max_s(S, px / Wn, px % Wn);
        masked[j] = (sc[j] >= lm && sc[j] > 0.05f) ? sc[j] : 0.0f;
        g_anch[base + px] = 0.0f;
    }
    __syncthreads();

    for (int k = 0; k < TOPKn; k++) {
        float v = -FLT_MAX; int bi = 0x7fffffff;
#pragma unroll
        for (int j = 0; j < 9; j++) {
            float m = masked[j]; int ix = tid + j*1024;
            if (m > v || (m == v && ix < bi)) { v = m; bi = ix; }
        }
#pragma unroll
        for (int off = 16; off; off >>= 1) {
            float ov = __shfl_down_sync(0xffffffffu, v, off);
            int   oi = __shfl_down_sync(0xffffffffu, bi, off);
            if (ov > v || (ov == v && oi < bi)) { v = ov; bi = oi; }
        }
        if (!lane) { rv[warp] = v; ri[warp] = bi; }
        __syncthreads();
        if (tid < 32) {
            v = rv[lane]; bi = ri[lane];
#pragma unroll
            for (int off = 16; off; off >>= 1) {
                float ov = __shfl_down_sync(0xffffffffu, v, off);
                int   oi = __shfl_down_sync(0xffffffffu, bi, off);
                if (ov > v || (ov == v && oi < bi)) { v = ov; bi = oi; }
            }
            if (!lane) { s_val[k] = v; s_idx[k] = bi; s_bi = bi; }
        }
        __syncthreads();
        int win = s_bi;
        if ((win & 1023) == tid) masked[win >> 10] = -FLT_MAX;
    }
    __syncthreads();

    if (tid < TOPKn) {
        float v = s_val[tid];
        int   ix = s_idx[tid];
        g_anch[base + ix] = v;
        float f[Rn];
#pragma unroll
        for (int r = 0; r < Rn; r++)
            f[r] = g_proj[((size_t)b*Rn + r) * HWn + ix];
        float best = -FLT_MAX; int bp = 0;
#pragma unroll
        for (int p = 0; p < Pn; p++) {
            float l = 0.0f;
#pragma unroll
            for (int r = 0; r < Rn; r++) l += f[r] * sprot[p*Rn + r];
            if (l > best) { best = l; bp = p; }
        }
        spidx[tid] = bp;
    }
    __syncthreads();

    for (int wk = tid; wk < TOPKn * KSn * KSn; wk += 1024) {
        int a = wk / (KSn*KSn);
        int t = wk - a * (KSn*KSn);
        float val = s_val[a];
        if (val <= 0.0f) continue;
        int idx = s_idx[a];
        int pi  = spidx[a];
        int ys = idx / Wn, xs = idx % Wn;
        int dy = t / KSn, dx = t % KSn;
        int y = ys + dy - KSn/2, x = xs + dx - KSn/2;
        if (y < 0 || y >= Hn || x < 0 || x >= Wn) continue;
        float gx  = (float)(-1.0 + (double)dx * (2.0 / 12.0));
        float gy  = (float)(-1.0 + (double)dy * (2.0 / 12.0));
        float ori = (float)((double)pi * (3.14159265358979323846 / 16.0));
        float ln  = c_lenL[pi & 3];
        float wd  = c_widL[(pi >> 2) & 3];
        float c = cosf(ori), s = sinf(ori);
        float xr =  c * gx + s * gy;
        float yr = -s * gx + c * gy;
        float txx = xr / ln, tyy = yr / wd;
        float foot = expf(-(txx*txx) - (tyy*tyy)) * val;
        float* cv = g_canvas + (size_t)b * Rn * HWn + y*Wn + x;
#pragma unroll
        for (int r = 0; r < Rn; r++)
            atomicAdd(cv + (size_t)r * HWn, sprot[pi*Rn + r] * foot);
    }
}

// ---------------- final: (16->12 gelu)->(12->768), f-split x2, 4 acc chains ----------------
__global__ void __launch_bounds__(128) k_final(const float* __restrict__ w3,
                                               const float* __restrict__ b3,
                                               const float* __restrict__ w4,
                                               const float* __restrict__ b4,
                                               float* __restrict__ outp) {
    __shared__ __align__(16) ull wint[192*12];
    __shared__ ull bp4[192];
    __shared__ float sw3[Rn*16];
    __shared__ float sb3[Rn];

    int bx = blockIdx.x;
    int fh = bx & 1;
    int t2 = bx >> 1;
    int b  = t2 / 36;
    int f0 = fh * 384;
    {
        float* wf = (float*)wint;
        for (int i = threadIdx.x; i < 384*Rn; i += 128) {
            int fl = i / Rn, r = i - fl*Rn;
            wf[(fl >> 1)*24 + r*2 + (fl & 1)] = w4[(f0 + fl)*Rn + r];
        }
        float* bf = (float*)bp4;
        for (int i = threadIdx.x; i < 384; i += 128) bf[i] = b4[f0 + i];
        for (int i = threadIdx.x; i < Rn*16; i += 128) sw3[i] = w3[i];
        for (int i = threadIdx.x; i < Rn;    i += 128) sb3[i] = b3[i];
    }
    __syncthreads();

    int p0 = (t2 % 36) * 256 + threadIdx.x * 2;
    size_t bpx = (size_t)b * HWn + p0;

    float2 sup = *(const float2*)(g_sup + bpx);
    float2 occ = *(const float2*)(g_occ + bpx);
    float2 an  = *(const float2*)(g_anch + bpx);
    float2 dn  = *(const float2*)(g_dnorm + bpx);

    float in0[16], in1[16];
#pragma unroll
    for (int r = 0; r < Rn; r++) {
        float2 cv = *(const float2*)(g_canvas + ((size_t)b*Rn + r) * HWn + p0);
        in0[r] = cv.x * sup.x;
        in1[r] = cv.y * sup.y;
    }
    in0[12] = occ.x; in1[12] = occ.y;
    in0[13] = sup.x; in1[13] = sup.y;
    in0[14] = an.x;  in1[14] = an.y;
    in0[15] = dn.x;  in1[15] = dn.y;

    ull md0[Rn], md1[Rn];
#pragma unroll
    for (int r = 0; r < Rn; r++) {
        float m0 = sb3[r], m1 = sb3[r];
#pragma unroll
        for (int j = 0; j < 16; j++) {
            float w = sw3[r*16 + j];
            m0 += in0[j] * w;
            m1 += in1[j] * w;
        }
        md0[r] = dup2(gelu_exact(m0));
        md1[r] = dup2(gelu_exact(m1));
    }

    float* ob = outp + (size_t)b * FCn * HWn + (size_t)f0 * HWn + p0;
    const ulonglong2* wv = (const ulonglong2*)wint;
#pragma unroll 2
    for (int fp = 0; fp < 192; fp += 2) {
        ull a0 = bp4[fp];
        ull a1 = a0;
        ull a2 = bp4[fp + 1];
        ull a3 = a2;
        const ulonglong2* w = wv + fp*6;
#pragma unroll
        for (int q = 0; q < 6; q++) {
            ulonglong2 wq = w[q];
            ulonglong2 w2 = w[q + 6];
            ffma2(a0, md0[2*q],     wq.x);
            ffma2(a1, md1[2*q],     wq.x);
            ffma2(a2, md0[2*q],     w2.x);
            ffma2(a3, md1[2*q],     w2.x);
            ffma2(a0, md0[2*q + 1], wq.y);
            ffma2(a1, md1[2*q + 1], wq.y);
            ffma2(a2, md0[2*q + 1], w2.y);
            ffma2(a3, md1[2*q + 1], w2.y);
        }
        float2 u0 = unpack2(a0), u1 = unpack2(a1);
        float2 u2 = unpack2(a2), u3 = unpack2(a3);
        float2 v0; v0.x = u0.x; v0.y = u1.x;
        float2 v1; v1.x = u0.y; v1.y = u1.y;
        float2 v2; v2.x = u2.x; v2.y = u3.x;
        float2 v3; v3.x = u2.y; v3.y = u3.y;
        *(float2*)(ob + (size_t)(2*fp)     * HWn) = v0;
        *(float2*)(ob + (size_t)(2*fp + 1) * HWn) = v1;
        *(float2*)(ob + (size_t)(2*fp + 2) * HWn) = v2;
        *(float2*)(ob + (size_t)(2*fp + 3) * HWn) = v3;
    }
}

// ---------------- launch ----------------
extern "C" void kernel_launch(void* const* d_in, const int* in_sizes, int n_in,
                              void* d_out, int out_size) {
    const float* features = (const float*)d_in[0];
    const float* carrier  = (const float*)d_in[1];
    const float* density  = (const float*)d_in[2];
    const float* w1 = (const float*)d_in[3];
    const float* b1 = (const float*)d_in[4];
    const float* w2 = (const float*)d_in[5];
    const float* b2 = (const float*)d_in[6];
    const float* w3 = (const float*)d_in[7];
    const float* b3 = (const float*)d_in[8];
    const float* w4 = (const float*)d_in[9];
    const float* b4 = (const float*)d_in[10];
    const float* proto = (const float*)d_in[11];
    float* outp = (float*)d_out;

    // 3 empty slot-shifters so conv1 lands in the ncu capture slot (index 3)
    k_nop0<<<1, 32>>>();
    k_nop1<<<1, 32>>>();
    k_nop2<<<1, 32>>>();
    k_conv1<<<144, 256>>>(features, w1, b1);
    k_conv2<<<dim3(6, 6, 8), 256>>>(w2, b2);
    k_fused<<<Bn, 1024>>>(carrier, density, proto);
    k_final<<<576, 128>>>(w3, b3, w4, b4, outp);
}

// round 14
// speedup vs baseline: 1.0060x; 1.0060x over previous
#include <cuda_runtime.h>
#include <math.h>
#include <float.h>

#define Bn    8
#define Hn    96
#define Wn    96
#define HWn   9216
#define FCn   768
#define Rn    12
#define Pn    16
#define KSn   13
#define TOPKn 24

typedef unsigned long long ull;

// ---------------- scratch (device globals) ----------------
__device__ float g_t1[Bn*Rn*HWn];
__device__ float g_proj[Bn*Rn*HWn];
__device__ float g_canvas[Bn*Rn*HWn];
__device__ float g_occraw[Bn*HWn];
__device__ float g_sup[Bn*HWn];
__device__ float g_occ[Bn*HWn];
__device__ float g_dnorm[Bn*HWn];
__device__ float g_anch[Bn*HWn];

// ---------------- helpers ----------------
__device__ __forceinline__ void ffma2(ull &acc, ull a, ull b) {
    asm("fma.rn.f32x2 %0, %1, %2, %0;" : "+l"(acc) : "l"(a), "l"(b));
}
__device__ __forceinline__ ull dup2(float x) {
    ull r;
    asm("mov.b64 %0, {%1, %1};" : "=l"(r) : "f"(x));
    return r;
}
__device__ __forceinline__ float2 unpack2(ull v) {
    float2 r;
    asm("mov.b64 {%0, %1}, %2;" : "=f"(r.x), "=f"(r.y) : "l"(v));
    return r;
}
__device__ __forceinline__ float gelu_exact(float x) {
    return 0.5f * x * (1.0f + erff(x * 0.70710678118654752440f));
}

// ---------------- K1: conv1x1 FC->R + gelu ----------------
// 288 blocks x 128 thr x 2 px: same 2-px COMP8 arithmetic as the 174.2us best,
// but 4-5 CTAs/SM (16-20 warps) to cover DRAM latency (conv1 measured issue=28%).
__global__ void __launch_bounds__(128) k_conv1(const float* __restrict__ feat,
                                               const float* __restrict__ w1,
                                               const float* __restrict__ b1) {
    __shared__ __align__(16) float sw[FCn*Rn];   // [c][r] contiguous 12 floats/channel
    for (int i = threadIdx.x; i < FCn*Rn; i += 128) {
        int c = i / Rn, r = i - c*Rn;
        sw[i] = w1[r*FCn + c];
    }
    __syncthreads();
    int b  = blockIdx.x / 36;
    int p0 = (blockIdx.x % 36) * 256 + threadIdx.x * 2;
    const float* fb = feat + (size_t)b * FCn * HWn + p0;

    ull acc0[6], acc1[6];
#pragma unroll
    for (int j = 0; j < 6; j++) { acc0[j] = 0ull; acc1[j] = 0ull; }

    const ulonglong2* wv = (const ulonglong2*)sw;  // 3 per channel

#define LOAD8(X, CH) do { \
    _Pragma("unroll") \
    for (int u_ = 0; u_ < 8; u_++) X[u_] = *(const float2*)(fb + (size_t)((CH) + u_) * HWn); \
} while (0)
#define COMP8(X, CH) do { \
    _Pragma("unroll") \
    for (int u_ = 0; u_ < 8; u_++) { \
        ull d0_ = dup2(X[u_].x); \
        ull d1_ = dup2(X[u_].y); \
        const ulonglong2* w_ = wv + ((CH) + u_) * 3; \
        ulonglong2 q0 = w_[0], q1 = w_[1], q2 = w_[2]; \
        ffma2(acc0[0], d0_, q0.x); ffma2(acc1[0], d1_, q0.x); \
        ffma2(acc0[1], d0_, q0.y); ffma2(acc1[1], d1_, q0.y); \
        ffma2(acc0[2], d0_, q1.x); ffma2(acc1[2], d1_, q1.x); \
        ffma2(acc0[3], d0_, q1.y); ffma2(acc1[3], d1_, q1.y); \
        ffma2(acc0[4], d0_, q2.x); ffma2(acc1[4], d1_, q2.x); \
        ffma2(acc0[5], d0_, q2.y); ffma2(acc1[5], d1_, q2.y); \
    } \
} while (0)

    float2 A[8], B[8], C[8];
    LOAD8(A, 0); LOAD8(B, 8); LOAD8(C, 16);
    int cb = 0;
#pragma unroll 1
    for (int it = 0; it < 31; it++) {
        COMP8(A, cb);      LOAD8(A, cb + 24);
        COMP8(B, cb + 8);  LOAD8(B, cb + 32);
        COMP8(C, cb + 16); LOAD8(C, cb + 40);
        cb += 24;
    }
    COMP8(A, 744); COMP8(B, 752); COMP8(C, 760);
#undef LOAD8
#undef COMP8

    float* op = g_t1 + (size_t)b * Rn * HWn + p0;
#pragma unroll
    for (int j = 0; j < 6; j++) {
        float2 a0 = unpack2(acc0[j]);
        float2 a1 = unpack2(acc1[j]);
        float bias0 = __ldg(b1 + 2*j), bias1 = __ldg(b1 + 2*j + 1);
        float2 s0; s0.x = gelu_exact(a0.x + bias0); s0.y = gelu_exact(a1.x + bias0);
        float2 s1; s1.x = gelu_exact(a0.y + bias1); s1.y = gelu_exact(a1.y + bias1);
        *(float2*)(op + (size_t)(2*j)     * HWn) = s0;
        *(float2*)(op + (size_t)(2*j + 1) * HWn) = s1;
    }
}

// ---------------- K2: conv3x3 R->R + gelu + occ_raw + canvas zero ----------------
__global__ void __launch_bounds__(256) k_conv2(const float* __restrict__ w2,
                                               const float* __restrict__ b2) {
    __shared__ float tile[Rn][18*18];
    __shared__ __align__(16) float sw2[Rn*Rn*9];
    __shared__ __align__(16) float sb2[Rn];
    int b   = blockIdx.z;
    int ty0 = blockIdx.y * 16, tx0 = blockIdx.x * 16;
    for (int i = threadIdx.x; i < Rn*Rn*9; i += 256) {
        int rout = i % 12;
        int rest = i / 12;
        int rin  = rest / 9;
        int k9   = rest % 9;
        sw2[i] = w2[(rout*12 + rin) * 9 + k9];
    }
    if (threadIdx.x < Rn) sb2[threadIdx.x] = b2[threadIdx.x];
    const float* tin = g_t1 + (size_t)b * Rn * HWn;
    for (int i = threadIdx.x; i < Rn*324; i += 256) {
        int ch = i / 324, rem = i - ch*324;
        int yy = rem / 18, xx = rem % 18;
        int gy = ty0 + yy - 1, gx = tx0 + xx - 1;
        float v = 0.0f;
        if (gy >= 0 && gy < Hn && gx >= 0 && gx < Wn)
            v = tin[(size_t)ch * HWn + gy*Wn + gx];
        tile[ch][rem] = v;
    }
    __syncthreads();
    int ty = threadIdx.x / 16, tx = threadIdx.x % 16;
    ull acc[6];
    {
        const ull* bb = (const ull*)sb2;
#pragma unroll
        for (int j = 0; j < 6; j++) acc[j] = bb[j];
    }
    const ulonglong2* wv = (const ulonglong2*)sw2;
#pragma unroll
    for (int rin = 0; rin < 12; rin++) {
#pragma unroll
        for (int k9 = 0; k9 < 9; k9++) {
            int ky = k9 / 3, kx = k9 % 3;
            ull d = dup2(tile[rin][(ty + ky)*18 + tx + kx]);
            const ulonglong2* w = wv + (rin*9 + k9) * 3;
            ulonglong2 w0 = w[0], w1v = w[1], w2v = w[2];
            ffma2(acc[0], d, w0.x);  ffma2(acc[1], d, w0.y);
            ffma2(acc[2], d, w1v.x); ffma2(acc[3], d, w1v.y);
            ffma2(acc[4], d, w2v.x); ffma2(acc[5], d, w2v.y);
        }
    }
    int p = (ty0 + ty)*Wn + tx0 + tx;
    float* pout = g_proj + (size_t)b * Rn * HWn + p;
    float* cz   = g_canvas + (size_t)b * Rn * HWn + p;
    float asum = 0.0f;
#pragma unroll
    for (int j = 0; j < 6; j++) {
        float2 a = unpack2(acc[j]);
        float g0 = gelu_exact(a.x), g1 = gelu_exact(a.y);
        pout[(size_t)(2*j)     * HWn] = g0;
        pout[(size_t)(2*j + 1) * HWn] = g1;
        cz[(size_t)(2*j)     * HWn] = 0.0f;
        cz[(size_t)(2*j + 1) * HWn] = 0.0f;
        asum += fabsf(g0) + fabsf(g1);
    }
    g_occraw[b*HWn + p] = asum * (1.0f / 12.0f);
}

// ---------------- fused support/NMS/top-k/proto/stamp (1 block per batch) ----------------
__device__ __forceinline__ float win3max_s(const float* S, int y, int x) {
    float r = -FLT_MAX;
#pragma unroll
    for (int dy = -1; dy <= 1; dy++) {
        int yy = y + dy; if (yy < 0 || yy >= Hn) continue;
#pragma unroll
        for (int dx = -1; dx <= 1; dx++) {
            int xx = x + dx; if (xx < 0 || xx >= Wn) continue;
            r = fmaxf(r, S[yy*Wn + xx]);
        }
    }
    return r;
}
__device__ __forceinline__ float win3min_s(const float* S, int y, int x) {
    float r = FLT_MAX;
#pragma unroll
    for (int dy = -1; dy <= 1; dy++) {
        int yy = y + dy; if (yy < 0 || yy >= Hn) continue;
#pragma unroll
        for (int dx = -1; dx <= 1; dx++) {
            int xx = x + dx; if (xx < 0 || xx >= Wn) continue;
            r = fminf(r, S[yy*Wn + xx]);
        }
    }
    return r;
}
__device__ __forceinline__ float win3sum_s(const float* S, int y, int x) {
    float r = 0.0f;
#pragma unroll
    for (int dy = -1; dy <= 1; dy++) {
        int yy = y + dy; if (yy < 0 || yy >= Hn) continue;
#pragma unroll
        for (int dx = -1; dx <= 1; dx++) {
            int xx = x + dx; if (xx < 0 || xx >= Wn) continue;
            r += S[yy*Wn + xx];
        }
    }
    return r;
}

__device__ __constant__ float c_lenL[4] = {0.4f, 0.7f, 1.0f, 1.25f};
__device__ __constant__ float c_widL[4] = {0.12f, 0.18f, 0.24f, 0.3f};

__global__ void __launch_bounds__(1024) k_fused(const float* __restrict__ carrier,
                                                const float* __restrict__ density,
                                                const float* __restrict__ proto) {
    __shared__ float S[HWn];
    __shared__ float smn[32], smx[32];
    __shared__ float rv[32];
    __shared__ int   ri[32];
    __shared__ float sprot[Pn*Rn];
    __shared__ float s_val[TOPKn];
    __shared__ int   s_idx[TOPKn];
    __shared__ int   spidx[TOPKn];
    __shared__ int   s_bi;

    int b = blockIdx.x, tid = threadIdx.x;
    int lane = tid & 31, warp = tid >> 5;
    const size_t base = (size_t)b * HWn;

    if (tid < Pn*Rn) sprot[tid] = proto[tid];

    float dreg[9], oreg[9];
    float dmn = FLT_MAX, dmx = -FLT_MAX, omn = FLT_MAX, omx = -FLT_MAX;
#pragma unroll
    for (int j = 0; j < 9; j++) {
        int px = tid + j*1024;
        float d = density[base + px];
        float o = g_occraw[base + px];
        dreg[j] = d; oreg[j] = o;
        dmn = fminf(dmn, d); dmx = fmaxf(dmx, d);
        omn = fminf(omn, o); omx = fmaxf(omx, o);
        S[px] = fabsf(carrier[base + px]);
    }
#pragma unroll
    for (int off = 16; off; off >>= 1) {
        dmn = fminf(dmn, __shfl_down_sync(0xffffffffu, dmn, off));
        dmx = fmaxf(dmx, __shfl_down_sync(0xffffffffu, dmx, off));
        omn = fminf(omn, __shfl_down_sync(0xffffffffu, omn, off));
        omx = fmaxf(omx, __shfl_down_sync(0xffffffffu, omx, off));
    }
    if (!lane) { smn[warp] = dmn; smx[warp] = dmx; rv[warp] = omn; ri[warp] = __float_as_int(omx); }
    __syncthreads();
    if (tid < 32) {
        float a = smn[lane], c = smx[lane], e = rv[lane], f = __int_as_float(ri[lane]);
#pragma unroll
        for (int off = 16; off; off >>= 1) {
            a = fminf(a, __shfl_down_sync(0xffffffffu, a, off));
            c = fmaxf(c, __shfl_down_sync(0xffffffffu, c, off));
            e = fminf(e, __shfl_down_sync(0xffffffffu, e, off));
            f = fmaxf(f, __shfl_down_sync(0xffffffffu, f, off));
        }
        if (!lane) { smn[0] = a; smx[0] = c; rv[0] = e; ri[0] = __float_as_int(f); }
    }
    __syncthreads();
    dmn = smn[0]; dmx = smx[0]; omn = rv[0]; omx = __int_as_float(ri[0]);
    __syncthreads();

    float cav[9];
    float cmn = FLT_MAX, cmx = -FLT_MAX;
#pragma unroll
    for (int j = 0; j < 9; j++) {
        int px = tid + j*1024;
        int y = px / Wn, x = px - y*Wn;
        float v = win3sum_s(S, y, x) * (1.0f / 9.0f);
        cav[j] = v;
        cmn = fminf(cmn, v); cmx = fmaxf(cmx, v);
    }
#pragma unroll
    for (int off = 16; off; off >>= 1) {
        cmn = fminf(cmn, __shfl_down_sync(0xffffffffu, cmn, off));
        cmx = fmaxf(cmx, __shfl_down_sync(0xffffffffu, cmx, off));
    }
    if (!lane) { smn[warp] = cmn; smx[warp] = cmx; }
    __syncthreads();
    if (tid < 32) {
        float a = smn[lane], c = smx[lane];
#pragma unroll
        for (int off = 16; off; off >>= 1) {
            a = fminf(a, __shfl_down_sync(0xffffffffu, a, off));
            c = fmaxf(c, __shfl_down_sync(0xffffffffu, c, off));
        }
        if (!lane) { smn[0] = a; smx[0] = c; }
    }
    __syncthreads();
    cmn = smn[0]; cmx = smx[0];

    float dinv = 1.0f / fmaxf(dmx - dmn, 1e-6f);
    float oinv = 1.0f / fmaxf(omx - omn, 1e-6f);
    float cinv = 1.0f / fmaxf(cmx - cmn, 1e-6f);

    float occ[9], mval[9];
#pragma unroll
    for (int j = 0; j < 9; j++) {
        int px = tid + j*1024;
        float dn = (dreg[j] - dmn) * dinv;
        float oc = (oreg[j] - omn) * oinv;
        float cs = (cav[j] - cmn) * cinv;
        g_dnorm[base + px] = dn;
        g_occ[base + px] = oc;
        occ[j] = oc;
        float ev = 0.8f * cs + 0.2f * dn;
        mval[j] = (ev >= 0.28f) ? 1.0f : 0.0f;
    }
    __syncthreads();
#pragma unroll
    for (int j = 0; j < 9; j++) S[tid + j*1024] = mval[j];
    __syncthreads();
    float er[9];
#pragma unroll
    for (int j = 0; j < 9; j++) {
        int px = tid + j*1024;
        er[j] = win3min_s(S, px / Wn, px % Wn);
    }
    __syncthreads();
#pragma unroll
    for (int j = 0; j < 9; j++) S[tid + j*1024] = er[j];
    __syncthreads();
    float op[9];
#pragma unroll
    for (int j = 0; j < 9; j++) {
        int px = tid + j*1024;
        op[j] = fminf(fmaxf(win3max_s(S, px / Wn, px % Wn), 0.0f), 1.0f);
    }
    __syncthreads();
#pragma unroll
    for (int j = 0; j < 9; j++) S[tid + j*1024] = op[j];
    __syncthreads();
    float sc[9];
#pragma unroll
    for (int j = 0; j < 9; j++) {
        int px = tid + j*1024;
        float sp = fminf(fmaxf(win3max_s(S, px / Wn, px % Wn), 0.0f), 1.0f);
        g_sup[base + px] = sp;
        sc[j] = occ[j] * sp;
    }
    __syncthreads();
#pragma unroll
    for (int j = 0; j < 9; j++) S[tid + j*1024] = sc[j];
    __syncthreads();
    float masked[9];
#pragma unroll
    for (int j = 0; j < 9; j++) {
        int px = tid + j*1024;
        float lm = win3max_s(S, px / Wn, px % Wn);
        masked[j] = (sc[j] >= lm && sc[j] > 0.05f) ? sc[j] : 0.0f;
        g_anch[base + px] = 0.0f;
    }
    __syncthreads();

    for (int k = 0; k < TOPKn; k++) {
        float v = -FLT_MAX; int bi = 0x7fffffff;
#pragma unroll
        for (int j = 0; j < 9; j++) {
            float m = masked[j]; int ix = tid + j*1024;
            if (m > v || (m == v && ix < bi)) { v = m; bi = ix; }
        }
#pragma unroll
        for (int off = 16; off; off >>= 1) {
            float ov = __shfl_down_sync(0xffffffffu, v, off);
            int   oi = __shfl_down_sync(0xffffffffu, bi, off);
            if (ov > v || (ov == v && oi < bi)) { v = ov; bi = oi; }
        }
        if (!lane) { rv[warp] = v; ri[warp] = bi; }
        __syncthreads();
        if (tid < 32) {
            v = rv[lane]; bi = ri[lane];
#pragma unroll
            for (int off = 16; off; off >>= 1) {
                float ov = __shfl_down_sync(0xffffffffu, v, off);
                int   oi = __shfl_down_sync(0xffffffffu, bi, off);
                if (ov > v || (ov == v && oi < bi)) { v = ov; bi = oi; }
            }
            if (!lane) { s_val[k] = v; s_idx[k] = bi; s_bi = bi; }
        }
        __syncthreads();
        int win = s_bi;
        if ((win & 1023) == tid) masked[win >> 10] = -FLT_MAX;
    }
    __syncthreads();

    if (tid < TOPKn) {
        float v = s_val[tid];
        int   ix = s_idx[tid];
        g_anch[base + ix] = v;
        float f[Rn];
#pragma unroll
        for (int r = 0; r < Rn; r++)
            f[r] = g_proj[((size_t)b*Rn + r) * HWn + ix];
        float best = -FLT_MAX; int bp = 0;
#pragma unroll
        for (int p = 0; p < Pn; p++) {
            float l = 0.0f;
#pragma unroll
            for (int r = 0; r < Rn; r++) l += f[r] * sprot[p*Rn + r];
            if (l > best) { best = l; bp = p; }
        }
        spidx[tid] = bp;
    }
    __syncthreads();

    for (int wk = tid; wk < TOPKn * KSn * KSn; wk += 1024) {
        int a = wk / (KSn*KSn);
        int t = wk - a * (KSn*KSn);
        float val = s_val[a];
        if (val <= 0.0f) continue;
        int idx = s_idx[a];
        int pi  = spidx[a];
        int ys = idx / Wn, xs = idx % Wn;
        int dy = t / KSn, dx = t % KSn;
        int y = ys + dy - KSn/2, x = xs + dx - KSn/2;
        if (y < 0 || y >= Hn || x < 0 || x >= Wn) continue;
        float gx  = (float)(-1.0 + (double)dx * (2.0 / 12.0));
        float gy  = (float)(-1.0 + (double)dy * (2.0 / 12.0));
        float ori = (float)((double)pi * (3.14159265358979323846 / 16.0));
        float ln  = c_lenL[pi & 3];
        float wd  = c_widL[(pi >> 2) & 3];
        float c = cosf(ori), s = sinf(ori);
        float xr =  c * gx + s * gy;
        float yr = -s * gx + c * gy;
        float txx = xr / ln, tyy = yr / wd;
        float foot = expf(-(txx*txx) - (tyy*tyy)) * val;
        float* cv = g_canvas + (size_t)b * Rn * HWn + y*Wn + x;
#pragma unroll
        for (int r = 0; r < Rn; r++)
            atomicAdd(cv + (size_t)r * HWn, sprot[pi*Rn + r] * foot);
    }
}

// ---------------- final: (16->12 gelu)->(12->768), f-split x2, 4 acc chains ----------------
__global__ void __launch_bounds__(128) k_final(const float* __restrict__ w3,
                                               const float* __restrict__ b3,
                                               const float* __restrict__ w4,
                                               const float* __restrict__ b4,
                                               float* __restrict__ outp) {
    __shared__ __align__(16) ull wint[192*12];
    __shared__ ull bp4[192];
    __shared__ float sw3[Rn*16];
    __shared__ float sb3[Rn];

    int bx = blockIdx.x;
    int fh = bx & 1;
    int t2 = bx >> 1;
    int b  = t2 / 36;
    int f0 = fh * 384;
    {
        float* wf = (float*)wint;
        for (int i = threadIdx.x; i < 384*Rn; i += 128) {
            int fl = i / Rn, r = i - fl*Rn;
            wf[(fl >> 1)*24 + r*2 + (fl & 1)] = w4[(f0 + fl)*Rn + r];
        }
        float* bf = (float*)bp4;
        for (int i = threadIdx.x; i < 384; i += 128) bf[i] = b4[f0 + i];
        for (int i = threadIdx.x; i < Rn*16; i += 128) sw3[i] = w3[i];
        for (int i = threadIdx.x; i < Rn;    i += 128) sb3[i] = b3[i];
    }
    __syncthreads();

    int p0 = (t2 % 36) * 256 + threadIdx.x * 2;
    size_t bpx = (size_t)b * HWn + p0;

    float2 sup = *(const float2*)(g_sup + bpx);
    float2 occ = *(const float2*)(g_occ + bpx);
    float2 an  = *(const float2*)(g_anch + bpx);
    float2 dn  = *(const float2*)(g_dnorm + bpx);

    float in0[16], in1[16];
#pragma unroll
    for (int r = 0; r < Rn; r++) {
        float2 cv = *(const float2*)(g_canvas + ((size_t)b*Rn + r) * HWn + p0);
        in0[r] = cv.x * sup.x;
        in1[r] = cv.y * sup.y;
    }
    in0[12] = occ.x; in1[12] = occ.y;
    in0[13] = sup.x; in1[13] = sup.y;
    in0[14] = an.x;  in1[14] = an.y;
    in0[15] = dn.x;  in1[15] = dn.y;

    ull md0[Rn], md1[Rn];
#pragma unroll
    for (int r = 0; r < Rn; r++) {
        float m0 = sb3[r], m1 = sb3[r];
#pragma unroll
        for (int j = 0; j < 16; j++) {
            float w = sw3[r*16 + j];
            m0 += in0[j] * w;
            m1 += in1[j] * w;
        }
        md0[r] = dup2(gelu_exact(m0));
        md1[r] = dup2(gelu_exact(m1));
    }

    float* ob = outp + (size_t)b * FCn * HWn + (size_t)f0 * HWn + p0;
    const ulonglong2* wv = (const ulonglong2*)wint;
#pragma unroll 2
    for (int fp = 0; fp < 192; fp += 2) {
        ull a0 = bp4[fp];
        ull a1 = a0;
        ull a2 = bp4[fp + 1];
        ull a3 = a2;
        const ulonglong2* w = wv + fp*6;
#pragma unroll
        for (int q = 0; q < 6; q++) {
            ulonglong2 wq = w[q];
            ulonglong2 w2 = w[q + 6];
            ffma2(a0, md0[2*q],     wq.x);
            ffma2(a1, md1[2*q],     wq.x);
            ffma2(a2, md0[2*q],     w2.x);
            ffma2(a3, md1[2*q],     w2.x);
            ffma2(a0, md0[2*q + 1], wq.y);
            ffma2(a1, md1[2*q + 1], wq.y);
            ffma2(a2, md0[2*q + 1], w2.y);
            ffma2(a3, md1[2*q + 1], w2.y);
        }
        float2 u0 = unpack2(a0), u1 = unpack2(a1);
        float2 u2 = unpack2(a2), u3 = unpack2(a3);
        float2 v0; v0.x = u0.x; v0.y = u1.x;
        float2 v1; v1.x = u0.y; v1.y = u1.y;
        float2 v2; v2.x = u2.x; v2.y = u3.x;
        float2 v3; v3.x = u2.y; v3.y = u3.y;
        *(float2*)(ob + (size_t)(2*fp)     * HWn) = v0;
        *(float2*)(ob + (size_t)(2*fp + 1) * HWn) = v1;
        *(float2*)(ob + (size_t)(2*fp + 2) * HWn) = v2;
        *(float2*)(ob + (size_t)(2*fp + 3) * HWn) = v3;
    }
}

// ---------------- launch ----------------
extern "C" void kernel_launch(void* const* d_in, const int* in_sizes, int n_in,
                              void* d_out, int out_size) {
    const float* features = (const float*)d_in[0];
    const float* carrier  = (const float*)d_in[1];
    const float* density  = (const float*)d_in[2];
    const float* w1 = (const float*)d_in[3];
    const float* b1 = (const float*)d_in[4];
    const float* w2 = (const float*)d_in[5];
    const float* b2 = (const float*)d_in[6];
    const float* w3 = (const float*)d_in[7];
    const float* b3 = (const float*)d_in[8];
    const float* w4 = (const float*)d_in[9];
    const float* b4 = (const float*)d_in[10];
    const float* proto = (const float*)d_in[11];
    float* outp = (float*)d_out;

    k_conv1<<<288, 128>>>(features, w1, b1);
    k_conv2<<<dim3(6, 6, 8), 256>>>(w2, b2);
    k_fused<<<Bn, 1024>>>(carrier, density, proto);
    k_final<<<576, 128>>>(w3, b3, w4, b4, outp);
}

// round 15
// speedup vs baseline: 1.0271x; 1.0210x over previous
#include <cuda_runtime.h>
#include <math.h>
#include <float.h>

#define Bn    8
#define Hn    96
#define Wn    96
#define HWn   9216
#define FCn   768
#define Rn    12
#define Pn    16
#define KSn   13
#define TOPKn 24

typedef unsigned long long ull;

// ---------------- scratch (device globals) ----------------
__device__ float g_t1[Bn*Rn*HWn];
__device__ float g_proj[Bn*Rn*HWn];
__device__ float g_canvas[Bn*Rn*HWn];
__device__ float g_occraw[Bn*HWn];
__device__ float g_sup[Bn*HWn];
__device__ float g_occ[Bn*HWn];
__device__ float g_dnorm[Bn*HWn];
__device__ float g_anch[Bn*HWn];

// ---------------- helpers ----------------
__device__ __forceinline__ void ffma2(ull &acc, ull a, ull b) {
    asm("fma.rn.f32x2 %0, %1, %2, %0;" : "+l"(acc) : "l"(a), "l"(b));
}
__device__ __forceinline__ ull dup2(float x) {
    ull r;
    asm("mov.b64 %0, {%1, %1};" : "=l"(r) : "f"(x));
    return r;
}
__device__ __forceinline__ float2 unpack2(ull v) {
    float2 r;
    asm("mov.b64 {%0, %1}, %2;" : "=f"(r.x), "=f"(r.y) : "l"(v));
    return r;
}
__device__ __forceinline__ float gelu_exact(float x) {
    return 0.5f * x * (1.0f + erff(x * 0.70710678118654752440f));
}

// ---------------- K1: conv1x1 FC->R + gelu (174.2us-best version) ----------------
__global__ void __launch_bounds__(256) k_conv1(const float* __restrict__ feat,
                                               const float* __restrict__ w1,
                                               const float* __restrict__ b1) {
    __shared__ __align__(16) float sw[FCn*Rn];
    for (int i = threadIdx.x; i < FCn*Rn; i += 256) {
        int c = i / Rn, r = i - c*Rn;
        sw[i] = w1[r*FCn + c];
    }
    __syncthreads();
    int b  = blockIdx.x / 18;
    int p0 = (blockIdx.x % 18) * 512 + threadIdx.x * 2;
    const float* fb = feat + (size_t)b * FCn * HWn + p0;

    ull acc0[6], acc1[6];
#pragma unroll
    for (int j = 0; j < 6; j++) { acc0[j] = 0ull; acc1[j] = 0ull; }

    const ulonglong2* wv = (const ulonglong2*)sw;

#define LOAD8(X, CH) do { \
    _Pragma("unroll") \
    for (int u_ = 0; u_ < 8; u_++) X[u_] = *(const float2*)(fb + (size_t)((CH) + u_) * HWn); \
} while (0)
#define COMP8(X, CH) do { \
    _Pragma("unroll") \
    for (int u_ = 0; u_ < 8; u_++) { \
        ull d0_ = dup2(X[u_].x); \
        ull d1_ = dup2(X[u_].y); \
        const ulonglong2* w_ = wv + ((CH) + u_) * 3; \
        ulonglong2 q0 = w_[0], q1 = w_[1], q2 = w_[2]; \
        ffma2(acc0[0], d0_, q0.x); ffma2(acc1[0], d1_, q0.x); \
        ffma2(acc0[1], d0_, q0.y); ffma2(acc1[1], d1_, q0.y); \
        ffma2(acc0[2], d0_, q1.x); ffma2(acc1[2], d1_, q1.x); \
        ffma2(acc0[3], d0_, q1.y); ffma2(acc1[3], d1_, q1.y); \
        ffma2(acc0[4], d0_, q2.x); ffma2(acc1[4], d1_, q2.x); \
        ffma2(acc0[5], d0_, q2.y); ffma2(acc1[5], d1_, q2.y); \
    } \
} while (0)

    float2 A[8], B[8], C[8];
    LOAD8(A, 0); LOAD8(B, 8); LOAD8(C, 16);
    int cb = 0;
#pragma unroll 1
    for (int it = 0; it < 31; it++) {
        COMP8(A, cb);      LOAD8(A, cb + 24);
        COMP8(B, cb + 8);  LOAD8(B, cb + 32);
        COMP8(C, cb + 16); LOAD8(C, cb + 40);
        cb += 24;
    }
    COMP8(A, 744); COMP8(B, 752); COMP8(C, 760);
#undef LOAD8
#undef COMP8

    float* op = g_t1 + (size_t)b * Rn * HWn + p0;
#pragma unroll
    for (int j = 0; j < 6; j++) {
        float2 a0 = unpack2(acc0[j]);
        float2 a1 = unpack2(acc1[j]);
        float bias0 = __ldg(b1 + 2*j), bias1 = __ldg(b1 + 2*j + 1);
        float2 s0; s0.x = gelu_exact(a0.x + bias0); s0.y = gelu_exact(a1.x + bias0);
        float2 s1; s1.x = gelu_exact(a0.y + bias1); s1.y = gelu_exact(a1.y + bias1);
        *(float2*)(op + (size_t)(2*j)     * HWn) = s0;
        *(float2*)(op + (size_t)(2*j + 1) * HWn) = s1;
    }
}

// ---------------- K2: conv3x3 R->R + gelu + occ_raw + canvas zero ----------------
__global__ void __launch_bounds__(256) k_conv2(const float* __restrict__ w2,
                                               const float* __restrict__ b2) {
    __shared__ float tile[Rn][18*18];
    __shared__ __align__(16) float sw2[Rn*Rn*9];
    __shared__ __align__(16) float sb2[Rn];
    int b   = blockIdx.z;
    int ty0 = blockIdx.y * 16, tx0 = blockIdx.x * 16;
    for (int i = threadIdx.x; i < Rn*Rn*9; i += 256) {
        int rout = i % 12;
        int rest = i / 12;
        int rin  = rest / 9;
        int k9   = rest % 9;
        sw2[i] = w2[(rout*12 + rin) * 9 + k9];
    }
    if (threadIdx.x < Rn) sb2[threadIdx.x] = b2[threadIdx.x];
    const float* tin = g_t1 + (size_t)b * Rn * HWn;
    for (int i = threadIdx.x; i < Rn*324; i += 256) {
        int ch = i / 324, rem = i - ch*324;
        int yy = rem / 18, xx = rem % 18;
        int gy = ty0 + yy - 1, gx = tx0 + xx - 1;
        float v = 0.0f;
        if (gy >= 0 && gy < Hn && gx >= 0 && gx < Wn)
            v = tin[(size_t)ch * HWn + gy*Wn + gx];
        tile[ch][rem] = v;
    }
    __syncthreads();
    int ty = threadIdx.x / 16, tx = threadIdx.x % 16;
    ull acc[6];
    {
        const ull* bb = (const ull*)sb2;
#pragma unroll
        for (int j = 0; j < 6; j++) acc[j] = bb[j];
    }
    const ulonglong2* wv = (const ulonglong2*)sw2;
#pragma unroll
    for (int rin = 0; rin < 12; rin++) {
#pragma unroll
        for (int k9 = 0; k9 < 9; k9++) {
            int ky = k9 / 3, kx = k9 % 3;
            ull d = dup2(tile[rin][(ty + ky)*18 + tx + kx]);
            const ulonglong2* w = wv + (rin*9 + k9) * 3;
            ulonglong2 w0 = w[0], w1v = w[1], w2v = w[2];
            ffma2(acc[0], d, w0.x);  ffma2(acc[1], d, w0.y);
            ffma2(acc[2], d, w1v.x); ffma2(acc[3], d, w1v.y);
            ffma2(acc[4], d, w2v.x); ffma2(acc[5], d, w2v.y);
        }
    }
    int p = (ty0 + ty)*Wn + tx0 + tx;
    float* pout = g_proj + (size_t)b * Rn * HWn + p;
    float* cz   = g_canvas + (size_t)b * Rn * HWn + p;
    float asum = 0.0f;
#pragma unroll
    for (int j = 0; j < 6; j++) {
        float2 a = unpack2(acc[j]);
        float g0 = gelu_exact(a.x), g1 = gelu_exact(a.y);
        pout[(size_t)(2*j)     * HWn] = g0;
        pout[(size_t)(2*j + 1) * HWn] = g1;
        cz[(size_t)(2*j)     * HWn] = 0.0f;
        cz[(size_t)(2*j + 1) * HWn] = 0.0f;
        asum += fabsf(g0) + fabsf(g1);
    }
    g_occraw[b*HWn + p] = asum * (1.0f / 12.0f);
}

// ---------------- shared-map stencils ----------------
__device__ __forceinline__ float win3max_s(const float* S, int y, int x) {
    float r = -FLT_MAX;
#pragma unroll
    for (int dy = -1; dy <= 1; dy++) {
        int yy = y + dy; if (yy < 0 || yy >= Hn) continue;
#pragma unroll
        for (int dx = -1; dx <= 1; dx++) {
            int xx = x + dx; if (xx < 0 || xx >= Wn) continue;
            r = fmaxf(r, S[yy*Wn + xx]);
        }
    }
    return r;
}
__device__ __forceinline__ float win3min_s(const float* S, int y, int x) {
    float r = FLT_MAX;
#pragma unroll
    for (int dy = -1; dy <= 1; dy++) {
        int yy = y + dy; if (yy < 0 || yy >= Hn) continue;
#pragma unroll
        for (int dx = -1; dx <= 1; dx++) {
            int xx = x + dx; if (xx < 0 || xx >= Wn) continue;
            r = fminf(r, S[yy*Wn + xx]);
        }
    }
    return r;
}
__device__ __forceinline__ float win3sum_s(const float* S, int y, int x) {
    float r = 0.0f;
#pragma unroll
    for (int dy = -1; dy <= 1; dy++) {
        int yy = y + dy; if (yy < 0 || yy >= Hn) continue;
#pragma unroll
        for (int dx = -1; dx <= 1; dx++) {
            int xx = x + dx; if (xx < 0 || xx >= Wn) continue;
            r += S[yy*Wn + xx];
        }
    }
    return r;
}

// ---------------- K_support: carrier/density-only half (runs CONCURRENT with conv1/conv2) ----------------
__global__ void __launch_bounds__(1024) k_support(const float* __restrict__ carrier,
                                                  const float* __restrict__ density) {
    __shared__ float S[HWn];
    __shared__ float smn[32], smx[32];

    int b = blockIdx.x, tid = threadIdx.x;
    int lane = tid & 31, warp = tid >> 5;
    const size_t base = (size_t)b * HWn;

    float dreg[9];
    float dmn = FLT_MAX, dmx = -FLT_MAX;
#pragma unroll
    for (int j = 0; j < 9; j++) {
        int px = tid + j*1024;
        float d = density[base + px];
        dreg[j] = d;
        dmn = fminf(dmn, d); dmx = fmaxf(dmx, d);
        S[px] = fabsf(carrier[base + px]);
        g_anch[base + px] = 0.0f;
    }
#pragma unroll
    for (int off = 16; off; off >>= 1) {
        dmn = fminf(dmn, __shfl_down_sync(0xffffffffu, dmn, off));
        dmx = fmaxf(dmx, __shfl_down_sync(0xffffffffu, dmx, off));
    }
    if (!lane) { smn[warp] = dmn; smx[warp] = dmx; }
    __syncthreads();
    if (tid < 32) {
        float a = smn[lane], c = smx[lane];
#pragma unroll
        for (int off = 16; off; off >>= 1) {
            a = fminf(a, __shfl_down_sync(0xffffffffu, a, off));
            c = fmaxf(c, __shfl_down_sync(0xffffffffu, c, off));
        }
        if (!lane) { smn[0] = a; smx[0] = c; }
    }
    __syncthreads();
    dmn = smn[0]; dmx = smx[0];
    __syncthreads();

    float cav[9];
    float cmn = FLT_MAX, cmx = -FLT_MAX;
#pragma unroll
    for (int j = 0; j < 9; j++) {
        int px = tid + j*1024;
        int y = px / Wn, x = px - y*Wn;
        float v = win3sum_s(S, y, x) * (1.0f / 9.0f);
        cav[j] = v;
        cmn = fminf(cmn, v); cmx = fmaxf(cmx, v);
    }
#pragma unroll
    for (int off = 16; off; off >>= 1) {
        cmn = fminf(cmn, __shfl_down_sync(0xffffffffu, cmn, off));
        cmx = fmaxf(cmx, __shfl_down_sync(0xffffffffu, cmx, off));
    }
    if (!lane) { smn[warp] = cmn; smx[warp] = cmx; }
    __syncthreads();
    if (tid < 32) {
        float a = smn[lane], c = smx[lane];
#pragma unroll
        for (int off = 16; off; off >>= 1) {
            a = fminf(a, __shfl_down_sync(0xffffffffu, a, off));
            c = fmaxf(c, __shfl_down_sync(0xffffffffu, c, off));
        }
        if (!lane) { smn[0] = a; smx[0] = c; }
    }
    __syncthreads();
    cmn = smn[0]; cmx = smx[0];

    float dinv = 1.0f / fmaxf(dmx - dmn, 1e-6f);
    float cinv = 1.0f / fmaxf(cmx - cmn, 1e-6f);

    float mval[9];
#pragma unroll
    for (int j = 0; j < 9; j++) {
        int px = tid + j*1024;
        float dn = (dreg[j] - dmn) * dinv;
        float cs = (cav[j] - cmn) * cinv;
        g_dnorm[base + px] = dn;
        float ev = 0.8f * cs + 0.2f * dn;
        mval[j] = (ev >= 0.28f) ? 1.0f : 0.0f;
    }
    __syncthreads();
#pragma unroll
    for (int j = 0; j < 9; j++) S[tid + j*1024] = mval[j];
    __syncthreads();
    float er[9];
#pragma unroll
    for (int j = 0; j < 9; j++) {
        int px = tid + j*1024;
        er[j] = win3min_s(S, px / Wn, px % Wn);
    }
    __syncthreads();
#pragma unroll
    for (int j = 0; j < 9; j++) S[tid + j*1024] = er[j];
    __syncthreads();
    float op[9];
#pragma unroll
    for (int j = 0; j < 9; j++) {
        int px = tid + j*1024;
        op[j] = fminf(fmaxf(win3max_s(S, px / Wn, px % Wn), 0.0f), 1.0f);
    }
    __syncthreads();
#pragma unroll
    for (int j = 0; j < 9; j++) S[tid + j*1024] = op[j];
    __syncthreads();
#pragma unroll
    for (int j = 0; j < 9; j++) {
        int px = tid + j*1024;
        float sp = fminf(fmaxf(win3max_s(S, px / Wn, px % Wn), 0.0f), 1.0f);
        g_sup[base + px] = sp;
    }
}

// ---------------- K_select: occ/scores/NMS/top-k/proto/stamp (after conv2 + support) ----------------
__device__ __constant__ float c_lenL[4] = {0.4f, 0.7f, 1.0f, 1.25f};
__device__ __constant__ float c_widL[4] = {0.12f, 0.18f, 0.24f, 0.3f};

__global__ void __launch_bounds__(1024) k_select(const float* __restrict__ proto) {
    __shared__ float S[HWn];
    __shared__ float smn[32], smx[32];
    __shared__ float rv[32];
    __shared__ int   ri[32];
    __shared__ float sprot[Pn*Rn];
    __shared__ float s_val[TOPKn];
    __shared__ int   s_idx[TOPKn];
    __shared__ int   spidx[TOPKn];
    __shared__ int   s_bi;

    int b = blockIdx.x, tid = threadIdx.x;
    int lane = tid & 31, warp = tid >> 5;
    const size_t base = (size_t)b * HWn;

    if (tid < Pn*Rn) sprot[tid] = proto[tid];

    float oreg[9];
    float omn = FLT_MAX, omx = -FLT_MAX;
#pragma unroll
    for (int j = 0; j < 9; j++) {
        int px = tid + j*1024;
        float o = g_occraw[base + px];
        oreg[j] = o;
        omn = fminf(omn, o); omx = fmaxf(omx, o);
    }
#pragma unroll
    for (int off = 16; off; off >>= 1) {
        omn = fminf(omn, __shfl_down_sync(0xffffffffu, omn, off));
        omx = fmaxf(omx, __shfl_down_sync(0xffffffffu, omx, off));
    }
    if (!lane) { smn[warp] = omn; smx[warp] = omx; }
    __syncthreads();
    if (tid < 32) {
        float a = smn[lane], c = smx[lane];
#pragma unroll
        for (int off = 16; off; off >>= 1) {
            a = fminf(a, __shfl_down_sync(0xffffffffu, a, off));
            c = fmaxf(c, __shfl_down_sync(0xffffffffu, c, off));
        }
        if (!lane) { smn[0] = a; smx[0] = c; }
    }
    __syncthreads();
    omn = smn[0]; omx = smx[0];
    float oinv = 1.0f / fmaxf(omx - omn, 1e-6f);

    float sc[9];
#pragma unroll
    for (int j = 0; j < 9; j++) {
        int px = tid + j*1024;
        float oc = (oreg[j] - omn) * oinv;
        g_occ[base + px] = oc;
        float sp = g_sup[base + px];
        sc[j] = oc * sp;
        S[px] = sc[j];
    }
    __syncthreads();
    float masked[9];
#pragma unroll
    for (int j = 0; j < 9; j++) {
        int px = tid + j*1024;
        float lm = win3max_s(S, px / Wn, px % Wn);
        masked[j] = (sc[j] >= lm && sc[j] > 0.05f) ? sc[j] : 0.0f;
    }
    __syncthreads();

    for (int k = 0; k < TOPKn; k++) {
        float v = -FLT_MAX; int bi = 0x7fffffff;
#pragma unroll
        for (int j = 0; j < 9; j++) {
            float m = masked[j]; int ix = tid + j*1024;
            if (m > v || (m == v && ix < bi)) { v = m; bi = ix; }
        }
#pragma unroll
        for (int off = 16; off; off >>= 1) {
            float ov = __shfl_down_sync(0xffffffffu, v, off);
            int   oi = __shfl_down_sync(0xffffffffu, bi, off);
            if (ov > v || (ov == v && oi < bi)) { v = ov; bi = oi; }
        }
        if (!lane) { rv[warp] = v; ri[warp] = bi; }
        __syncthreads();
        if (tid < 32) {
            v = rv[lane]; bi = ri[lane];
#pragma unroll
            for (int off = 16; off; off >>= 1) {
                float ov = __shfl_down_sync(0xffffffffu, v, off);
                int   oi = __shfl_down_sync(0xffffffffu, bi, off);
                if (ov > v || (ov == v && oi < bi)) { v = ov; bi = oi; }
            }
            if (!lane) { s_val[k] = v; s_idx[k] = bi; s_bi = bi; }
        }
        __syncthreads();
        int win = s_bi;
        if ((win & 1023) == tid) masked[win >> 10] = -FLT_MAX;
    }
    __syncthreads();

    if (tid < TOPKn) {
        float v = s_val[tid];
        int   ix = s_idx[tid];
        g_anch[base + ix] = v;
        float f[Rn];
#pragma unroll
        for (int r = 0; r < Rn; r++)
            f[r] = g_proj[((size_t)b*Rn + r) * HWn + ix];
        float best = -FLT_MAX; int bp = 0;
#pragma unroll
        for (int p = 0; p < Pn; p++) {
            float l = 0.0f;
#pragma unroll
            for (int r = 0; r < Rn; r++) l += f[r] * sprot[p*Rn + r];
            if (l > best) { best = l; bp = p; }
        }
        spidx[tid] = bp;
    }
    __syncthreads();

    for (int wk = tid; wk < TOPKn * KSn * KSn; wk += 1024) {
        int a = wk / (KSn*KSn);
        int t = wk - a * (KSn*KSn);
        float val = s_val[a];
        if (val <= 0.0f) continue;
        int idx = s_idx[a];
        int pi  = spidx[a];
        int ys = idx / Wn, xs = idx % Wn;
        int dy = t / KSn, dx = t % KSn;
        int y = ys + dy - KSn/2, x = xs + dx - KSn/2;
        if (y < 0 || y >= Hn || x < 0 || x >= Wn) continue;
        float gx  = (float)(-1.0 + (double)dx * (2.0 / 12.0));
        float gy  = (float)(-1.0 + (double)dy * (2.0 / 12.0));
        float ori = (float)((double)pi * (3.14159265358979323846 / 16.0));
        float ln  = c_lenL[pi & 3];
        float wd  = c_widL[(pi >> 2) & 3];
        float c = cosf(ori), s = sinf(ori);
        float xr =  c * gx + s * gy;
        float yr = -s * gx + c * gy;
        float txx = xr / ln, tyy = yr / wd;
        float foot = expf(-(txx*txx) - (tyy*tyy)) * val;
        float* cv = g_canvas + (size_t)b * Rn * HWn + y*Wn + x;
#pragma unroll
        for (int r = 0; r < Rn; r++)
            atomicAdd(cv + (size_t)r * HWn, sprot[pi*Rn + r] * foot);
    }
}

// ---------------- final: (16->12 gelu)->(12->768), f-split x2, 4 acc chains ----------------
__global__ void __launch_bounds__(128) k_final(const float* __restrict__ w3,
                                               const float* __restrict__ b3,
                                               const float* __restrict__ w4,
                                               const float* __restrict__ b4,
                                               float* __restrict__ outp) {
    __shared__ __align__(16) ull wint[192*12];
    __shared__ ull bp4[192];
    __shared__ float sw3[Rn*16];
    __shared__ float sb3[Rn];

    int bx = blockIdx.x;
    int fh = bx & 1;
    int t2 = bx >> 1;
    int b  = t2 / 36;
    int f0 = fh * 384;
    {
        float* wf = (float*)wint;
        for (int i = threadIdx.x; i < 384*Rn; i += 128) {
            int fl = i / Rn, r = i - fl*Rn;
            wf[(fl >> 1)*24 + r*2 + (fl & 1)] = w4[(f0 + fl)*Rn + r];
        }
        float* bf = (float*)bp4;
        for (int i = threadIdx.x; i < 384; i += 128) bf[i] = b4[f0 + i];
        for (int i = threadIdx.x; i < Rn*16; i += 128) sw3[i] = w3[i];
        for (int i = threadIdx.x; i < Rn;    i += 128) sb3[i] = b3[i];
    }
    __syncthreads();

    int p0 = (t2 % 36) * 256 + threadIdx.x * 2;
    size_t bpx = (size_t)b * HWn + p0;

    float2 sup = *(const float2*)(g_sup + bpx);
    float2 occ = *(const float2*)(g_occ + bpx);
    float2 an  = *(const float2*)(g_anch + bpx);
    float2 dn  = *(const float2*)(g_dnorm + bpx);

    float in0[16], in1[16];
#pragma unroll
    for (int r = 0; r < Rn; r++) {
        float2 cv = *(const float2*)(g_canvas + ((size_t)b*Rn + r) * HWn + p0);
        in0[r] = cv.x * sup.x;
        in1[r] = cv.y * sup.y;
    }
    in0[12] = occ.x; in1[12] = occ.y;
    in0[13] = sup.x; in1[13] = sup.y;
    in0[14] = an.x;  in1[14] = an.y;
    in0[15] = dn.x;  in1[15] = dn.y;

    ull md0[Rn], md1[Rn];
#pragma unroll
    for (int r = 0; r < Rn; r++) {
        float m0 = sb3[r], m1 = sb3[r];
#pragma unroll
        for (int j = 0; j < 16; j++) {
            float w = sw3[r*16 + j];
            m0 += in0[j] * w;
            m1 += in1[j] * w;
        }
        md0[r] = dup2(gelu_exact(m0));
        md1[r] = dup2(gelu_exact(m1));
    }

    float* ob = outp + (size_t)b * FCn * HWn + (size_t)f0 * HWn + p0;
    const ulonglong2* wv = (const ulonglong2*)wint;
#pragma unroll 2
    for (int fp = 0; fp < 192; fp += 2) {
        ull a0 = bp4[fp];
        ull a1 = a0;
        ull a2 = bp4[fp + 1];
        ull a3 = a2;
        const ulonglong2* w = wv + fp*6;
#pragma unroll
        for (int q = 0; q < 6; q++) {
            ulonglong2 wq = w[q];
            ulonglong2 w2 = w[q + 6];
            ffma2(a0, md0[2*q],     wq.x);
            ffma2(a1, md1[2*q],     wq.x);
            ffma2(a2, md0[2*q],     w2.x);
            ffma2(a3, md1[2*q],     w2.x);
            ffma2(a0, md0[2*q + 1], wq.y);
            ffma2(a1, md1[2*q + 1], wq.y);
            ffma2(a2, md0[2*q + 1], w2.y);
            ffma2(a3, md1[2*q + 1], w2.y);
        }
        float2 u0 = unpack2(a0), u1 = unpack2(a1);
        float2 u2 = unpack2(a2), u3 = unpack2(a3);
        float2 v0; v0.x = u0.x; v0.y = u1.x;
        float2 v1; v1.x = u0.y; v1.y = u1.y;
        float2 v2; v2.x = u2.x; v2.y = u3.x;
        float2 v3; v3.x = u2.y; v3.y = u3.y;
        *(float2*)(ob + (size_t)(2*fp)     * HWn) = v0;
        *(float2*)(ob + (size_t)(2*fp + 1) * HWn) = v1;
        *(float2*)(ob + (size_t)(2*fp + 2) * HWn) = v2;
        *(float2*)(ob + (size_t)(2*fp + 3) * HWn) = v3;
    }
}

// ---------------- side stream (host objects; created once before main) ----------------
struct StreamHolder {
    cudaStream_t s2 = nullptr;
    cudaEvent_t  evA = nullptr, evB = nullptr;
    bool ok = false;
    StreamHolder() {
        ok = (cudaStreamCreateWithFlags(&s2, cudaStreamNonBlocking) == cudaSuccess) &&
             (cudaEventCreateWithFlags(&evA, cudaEventDisableTiming) == cudaSuccess) &&
             (cudaEventCreateWithFlags(&evB, cudaEventDisableTiming) == cudaSuccess);
    }
};
static StreamHolder g_sh;

// ---------------- launch ----------------
extern "C" void kernel_launch(void* const* d_in, const int* in_sizes, int n_in,
                              void* d_out, int out_size) {
    const float* features = (const float*)d_in[0];
    const float* carrier  = (const float*)d_in[1];
    const float* density  = (const float*)d_in[2];
    const float* w1 = (const float*)d_in[3];
    const float* b1 = (const float*)d_in[4];
    const float* w2 = (const float*)d_in[5];
    const float* b2 = (const float*)d_in[6];
    const float* w3 = (const float*)d_in[7];
    const float* b3 = (const float*)d_in[8];
    const float* w4 = (const float*)d_in[9];
    const float* b4 = (const float*)d_in[10];
    const float* proto = (const float*)d_in[11];
    float* outp = (float*)d_out;

    cudaStream_t pt = cudaStreamPerThread;  // the stream <<<>>> targets under capture

    if (g_sh.ok) {
        // fork: support runs concurrent with conv1+conv2
        cudaEventRecord(g_sh.evA, pt);
        cudaStreamWaitEvent(g_sh.s2, g_sh.evA, 0);
        k_support<<<Bn, 1024, 0, g_sh.s2>>>(carrier, density);
        cudaEventRecord(g_sh.evB, g_sh.s2);

        k_conv1<<<144, 256, 0, pt>>>(features, w1, b1);
        k_conv2<<<dim3(6, 6, 8), 256, 0, pt>>>(w2, b2);

        // join
        cudaStreamWaitEvent(pt, g_sh.evB, 0);
        k_select<<<Bn, 1024, 0, pt>>>(proto);
        k_final<<<576, 128, 0, pt>>>(w3, b3, w4, b4, outp);
    } else {
        // deterministic sequential fallback
        k_support<<<Bn, 1024, 0, pt>>>(carrier, density);
        k_conv1<<<144, 256, 0, pt>>>(features, w1, b1);
        k_conv2<<<dim3(6, 6, 8), 256, 0, pt>>>(w2, b2);
        k_select<<<Bn, 1024, 0, pt>>>(proto);
        k_final<<<576, 128, 0, pt>>>(w3, b3, w4, b4, outp);
    }
}